// round 7
// baseline (speedup 1.0000x reference)
#include <cuda_runtime.h>
#include <cuda_bf16.h>
#include <cstdint>

#define NN 50000
#define FIN 256
#define HH 128
#define NHEAD 4
#define NL 3
#define NT 3
#define EE 250000
#define NEG 0.2f

// ---------------- device scratch ----------------
__device__ __align__(16) float g_x0[NN * HH];
__device__ __align__(16) __nv_bfloat16 g_xb[NN * HH];
__device__ __align__(16) __nv_bfloat16 g_xlr[(size_t)NT * NN * 1024];  // [t][n][xl512|xr512]
__device__ __align__(16) __nv_bfloat16 g_wlb[NL * NT * 128 * 512];
__device__ __align__(16) __nv_bfloat16 g_wrb[NL * NT * 128 * 512];
__device__ __align__(16) float g_agg[NN * HH];
__device__ int g_cnt[NT * NN];
__device__ int g_rs[NT * (NN + 1)];
__device__ int g_cur[NT * NN];
__device__ int g_csrc[NT * EE];
__device__ int g_is64;

__device__ __forceinline__ float lkf(float v) { return v > 0.f ? v : NEG * v; }

// ---------------- weight conversion f32 -> bf16 ----------------
__global__ void convw_kernel(const float* __restrict__ wl, const float* __restrict__ wr) {
  int i = blockIdx.x * 256 + threadIdx.x;
  if (i < NL * NT * 128 * 512) {
    g_wlb[i] = __float2bfloat16(wl[i]);
    g_wrb[i] = __float2bfloat16(wr[i]);
  }
}

// ---------------- precompute ----------------
__global__ void __launch_bounds__(128) precompute_kernel(
    const float* __restrict__ feat, const float* __restrict__ emb,
    const float* __restrict__ pw, const float* __restrict__ pb,
    const float* __restrict__ lng, const float* __restrict__ lnb) {
  __shared__ float sfeat[16][256];
  __shared__ float sh[16][132];
  const int tid = threadIdx.x;
  const int r0 = blockIdx.x * 16;

  for (int idx = tid; idx < 16 * 64; idx += 128) {
    int r = idx >> 6, k4 = idx & 63;
    float4 v = *(const float4*)&feat[(size_t)(r0 + r) * 256 + k4 * 4];
    *(float4*)&sfeat[r][k4 * 4] = v;
  }
  __syncthreads();

  float acc[16];
#pragma unroll
  for (int r = 0; r < 16; r++) acc[r] = 0.f;
  for (int k = 0; k < 256; k++) {
    float w = pw[k * 128 + tid];
#pragma unroll
    for (int r = 0; r < 16; r++) acc[r] = fmaf(sfeat[r][k], w, acc[r]);
  }
  float b = pb[tid];
#pragma unroll
  for (int r = 0; r < 16; r++) sh[r][tid] = acc[r] + b;
  __syncthreads();

  const int wid = tid >> 5, lane = tid & 31;
#pragma unroll 1
  for (int rr = 0; rr < 4; rr++) {
    int r = wid * 4 + rr;
    float v[4], e[4];
    float s = 0.f, s2 = 0.f, es = 0.f;
#pragma unroll
    for (int q = 0; q < 4; q++) {
      int c = lane + 32 * q;
      v[q] = sh[r][c];
      s += v[q];
      s2 += v[q] * v[q];
      e[q] = emb[(size_t)(r0 + r) * 128 + c];
      es += e[q] * e[q];
    }
#pragma unroll
    for (int off = 16; off; off >>= 1) {
      s += __shfl_xor_sync(0xffffffffu, s, off);
      s2 += __shfl_xor_sync(0xffffffffu, s2, off);
      es += __shfl_xor_sync(0xffffffffu, es, off);
    }
    float mu = s * (1.f / 128.f);
    float var = s2 * (1.f / 128.f) - mu * mu;
    float rst = rsqrtf(var + 1e-5f);
    float inv = 1.f / fmaxf(sqrtf(es), 1e-12f);
#pragma unroll
    for (int q = 0; q < 4; q++) {
      int c = lane + 32 * q;
      float hn = (v[q] - mu) * rst * lng[c] + lnb[c];
      float x0 = 0.7f * lkf(hn) + 0.5f * e[q] * inv;
      size_t o = (size_t)(r0 + r) * 128 + c;
      g_x0[o] = x0;
      g_xb[o] = __float2bfloat16(x0);
    }
  }
}

// ---------------- edge index dtype detection ----------------
__global__ void detect_kernel(const int* __restrict__ ed) {
  __shared__ int so;
  int tid = threadIdx.x;
  if (tid == 0) so = 0;
  __syncthreads();
  int o = 0;
  for (int i = tid; i < 4096; i += blockDim.x) o |= ed[2 * i + 1];
  atomicOr(&so, o);
  __syncthreads();
  if (tid == 0) g_is64 = (so == 0) ? 1 : 0;
}

__device__ __forceinline__ int load_idx(const int* p, int i, int is64) {
  return is64 ? (int)((const long long*)p)[i] : p[i];
}

// ---------------- CSR build ----------------
__global__ void zero_cnt_kernel() {
  int i = blockIdx.x * blockDim.x + threadIdx.x;
  if (i < NT * NN) g_cnt[i] = 0;
}

__global__ void hist_kernel(const int* __restrict__ edst) {
  int i = blockIdx.x * blockDim.x + threadIdx.x;
  if (i >= NT * EE) return;
  int is64 = g_is64;
  int t = i / EE;
  int d = load_idx(edst, i, is64);
  atomicAdd(&g_cnt[t * NN + d], 1);
}

__global__ void __launch_bounds__(1024) scan_kernel() {
  const int t = blockIdx.x;
  const int tid = threadIdx.x;
  __shared__ int sp[1024];
  const int C = (NN + 1023) / 1024;
  int b = tid * C;
  int e = min(b + C, NN);
  int s = 0;
  for (int v = b; v < e; v++) s += g_cnt[t * NN + v];
  sp[tid] = s;
  __syncthreads();
  for (int off = 1; off < 1024; off <<= 1) {
    int v = (tid >= off) ? sp[tid - off] : 0;
    __syncthreads();
    sp[tid] += v;
    __syncthreads();
  }
  int run = (tid ? sp[tid - 1] : 0);
  for (int v = b; v < e; v++) {
    g_rs[t * (NN + 1) + v] = run;
    g_cur[t * NN + v] = run;
    run += g_cnt[t * NN + v];
  }
  if (b < NN && e == NN) g_rs[t * (NN + 1) + NN] = run;
}

__global__ void scatter_kernel(const int* __restrict__ esrc, const int* __restrict__ edst) {
  int i = blockIdx.x * blockDim.x + threadIdx.x;
  if (i >= NT * EE) return;
  int is64 = g_is64;
  int t = i / EE;
  int d = load_idx(edst, i, is64);
  int slot = atomicAdd(&g_cur[t * NN + d], 1);
  g_csrc[t * EE + slot] = load_idx(esrc, i, is64);
}

// ---------------- bf16 tensor-core GEMM (m16n8k16 + ldmatrix), per type ----------------
#define AL 136
#define GEMM_SMEM (2 * 128 * AL * 2)

__global__ void __launch_bounds__(256, 2) gemm_bf16_kernel(int layer, int t) {
  extern __shared__ __nv_bfloat16 sm[];
  __nv_bfloat16* sA = sm;             // [128][AL]
  __nv_bfloat16* sB = sm + 128 * AL;  // [128][AL]
  const int tid = threadIdx.x;
  const int lane = tid & 31;
  const int wid = tid >> 5;
  const int warpM = wid >> 2, warpN = wid & 3;
  const int g = lane >> 2, tg = lane & 3;
  const int m0 = blockIdx.x * 128;
  const int j0 = blockIdx.y * 128;  // within [0,1024): lr*512 + col0
  const int lr = j0 >> 9;
  const int col0 = j0 & 511;
  const __nv_bfloat16* Wg = (lr ? g_wrb : g_wlb) + (size_t)(layer * 3 + t) * 65536 + col0;

#pragma unroll
  for (int it = 0; it < 8; it++) {
    int idx = tid + it * 256;
    int m = idx >> 4, k8 = (idx & 15) * 8;
    uint4 v = make_uint4(0, 0, 0, 0);
    if (m0 + m < NN) v = *(const uint4*)&g_xb[(size_t)(m0 + m) * 128 + k8];
    *(uint4*)&sA[m * AL + k8] = v;
    uint4 w = *(const uint4*)&Wg[(size_t)m * 512 + k8];
    *(uint4*)&sB[m * AL + k8] = w;
  }
  __syncthreads();

  float acc[4][4][4];
#pragma unroll
  for (int im = 0; im < 4; im++)
#pragma unroll
    for (int in = 0; in < 4; in++)
#pragma unroll
      for (int q = 0; q < 4; q++) acc[im][in][q] = 0.f;

  uint32_t aBase = (uint32_t)__cvta_generic_to_shared(sA);
  uint32_t bBase = (uint32_t)__cvta_generic_to_shared(sB);
  const int lrow = lane & 15, lcol = (lane >> 4) * 8;

#pragma unroll
  for (int k0 = 0; k0 < 8; k0++) {
    uint32_t a[4][4];
#pragma unroll
    for (int im = 0; im < 4; im++) {
      uint32_t ad = aBase + ((warpM * 64 + im * 16 + lrow) * AL + k0 * 16 + lcol) * 2;
      asm volatile("ldmatrix.sync.aligned.m8n8.x4.shared.b16 {%0,%1,%2,%3},[%4];"
                   : "=r"(a[im][0]), "=r"(a[im][1]), "=r"(a[im][2]), "=r"(a[im][3])
                   : "r"(ad));
    }
    uint32_t b[4][2];
#pragma unroll
    for (int nb = 0; nb < 2; nb++) {
      uint32_t bd = bBase + ((k0 * 16 + lrow) * AL + warpN * 32 + nb * 16 + lcol) * 2;
      uint32_t r0, r1, r2, r3;
      asm volatile("ldmatrix.sync.aligned.m8n8.x4.trans.shared.b16 {%0,%1,%2,%3},[%4];"
                   : "=r"(r0), "=r"(r1), "=r"(r2), "=r"(r3)
                   : "r"(bd));
      b[nb * 2][0] = r0;
      b[nb * 2][1] = r1;
      b[nb * 2 + 1][0] = r2;
      b[nb * 2 + 1][1] = r3;
    }
#pragma unroll
    for (int im = 0; im < 4; im++)
#pragma unroll
      for (int in = 0; in < 4; in++) {
        asm volatile(
            "mma.sync.aligned.m16n8k16.row.col.f32.bf16.bf16.f32 "
            "{%0,%1,%2,%3},{%4,%5,%6,%7},{%8,%9},{%0,%1,%2,%3};"
            : "+f"(acc[im][in][0]), "+f"(acc[im][in][1]),
              "+f"(acc[im][in][2]), "+f"(acc[im][in][3])
            : "r"(a[im][0]), "r"(a[im][1]), "r"(a[im][2]), "r"(a[im][3]),
              "r"(b[in][0]), "r"(b[in][1]));
      }
  }
  __syncthreads();

#pragma unroll
  for (int im = 0; im < 4; im++)
#pragma unroll
    for (int in = 0; in < 4; in++) {
      int r = warpM * 64 + im * 16 + g;
      int c = warpN * 32 + in * 8 + tg * 2;
      *(__nv_bfloat162*)&sA[r * AL + c] =
          __floats2bfloat162_rn(acc[im][in][0], acc[im][in][1]);
      *(__nv_bfloat162*)&sA[(r + 8) * AL + c] =
          __floats2bfloat162_rn(acc[im][in][2], acc[im][in][3]);
    }
  __syncthreads();
#pragma unroll
  for (int it = 0; it < 8; it++) {
    int idx = tid + it * 256;
    int m = idx >> 4, n8 = (idx & 15) * 8;
    if (m0 + m < NN) {
      uint4 v = *(uint4*)&sA[m * AL + n8];
      *(uint4*)&g_xlr[((size_t)t * NN + (m0 + m)) * 1024 + lr * 512 + col0 + n8] = v;
    }
  }
}

// ---------------- edge attention: warp/node, head-major lanes, per type ----------------
__device__ __forceinline__ void cvt16(const uint4& a, const uint4& b, float* o) {
  const uint32_t* u = &a.x;
#pragma unroll
  for (int q = 0; q < 4; q++) {
    float2 f = __bfloat1622float2(*reinterpret_cast<const __nv_bfloat162*>(&u[q]));
    o[q * 2] = f.x;
    o[q * 2 + 1] = f.y;
  }
  const uint32_t* v = &b.x;
#pragma unroll
  for (int q = 0; q < 4; q++) {
    float2 f = __bfloat1622float2(*reinterpret_cast<const __nv_bfloat162*>(&v[q]));
    o[8 + q * 2] = f.x;
    o[8 + q * 2 + 1] = f.y;
  }
}

__global__ void __launch_bounds__(256) edge_attn_kernel(int layer, int t,
                                                        const float* __restrict__ att,
                                                        const float* __restrict__ bias_) {
  const int w = (blockIdx.x * blockDim.x + threadIdx.x) >> 5;
  const int lane = threadIdx.x & 31;
  if (w >= NN) return;
  const int h = lane >> 3;
  const int c0 = (lane & 7) * 16;
  const int hoff = h * 128 + c0;
  const __nv_bfloat16* base = g_xlr + (size_t)t * NN * 1024;

  float af[16], xr[16], acc[16];
  {
    const float* a = att + (size_t)(layer * 3 + t) * 512 + hoff;
#pragma unroll
    for (int q = 0; q < 4; q++) {
      float4 v = *(const float4*)&a[q * 4];
      af[q * 4] = v.x; af[q * 4 + 1] = v.y; af[q * 4 + 2] = v.z; af[q * 4 + 3] = v.w;
    }
    const uint4* xp = (const uint4*)(base + (size_t)w * 1024 + 512 + hoff);
    cvt16(xp[0], xp[1], xr);
#pragma unroll
    for (int i = 0; i < 16; i++) acc[i] = 0.f;
  }
  float mx = -3.0e38f, dn = 0.f;

  const int beg = g_rs[t * (NN + 1) + w];
  const int end = g_rs[t * (NN + 1) + w + 1];
  const int* csr = g_csrc + (size_t)t * EE;

  uint4 p0, p1;
  if (beg < end) {
    const uint4* xp = (const uint4*)(base + (size_t)csr[beg] * 1024 + hoff);
    p0 = xp[0];
    p1 = xp[1];
  }
  for (int j = beg; j < end; j++) {
    uint4 c0v = p0, c1v = p1;
    if (j + 1 < end) {
      const uint4* xp = (const uint4*)(base + (size_t)csr[j + 1] * 1024 + hoff);
      p0 = xp[0];
      p1 = xp[1];
    }
    float xl[16];
    cvt16(c0v, c1v, xl);
    float part = 0.f;
#pragma unroll
    for (int i = 0; i < 16; i++) part = fmaf(af[i], lkf(xl[i] + xr[i]), part);
    part += __shfl_xor_sync(0xffffffffu, part, 1);
    part += __shfl_xor_sync(0xffffffffu, part, 2);
    part += __shfl_xor_sync(0xffffffffu, part, 4);

    float nm = fmaxf(mx, part);
    float sc = __expf(mx - nm);
    float p = __expf(part - nm);
    mx = nm;
    dn = dn * sc + p;
#pragma unroll
    for (int i = 0; i < 16; i++) acc[i] = acc[i] * sc + p * xl[i];
  }

  float s = (1.f / (dn + 1e-16f)) * 0.25f;
#pragma unroll
  for (int i = 0; i < 16; i++) acc[i] *= s;
  // head mean: butterfly over head bits (lanes ±8, ±16); all lanes get the mean
#pragma unroll
  for (int i = 0; i < 16; i++) {
    acc[i] += __shfl_xor_sync(0xffffffffu, acc[i], 8);
    acc[i] += __shfl_xor_sync(0xffffffffu, acc[i], 16);
  }
  // distribute the 16 channels across the 4 head-lanes: 4 atomics per lane
  const int sub = h * 4;
  const float* bs = bias_ + (size_t)(layer * 3 + t) * 128 + c0;
  float* dst = &g_agg[(size_t)w * 128 + c0];
#pragma unroll
  for (int q = 0; q < 4; q++) {
    int i = sub + q;
    atomicAdd(&dst[i], acc[i] + bs[i]);
  }
}

// ---------------- layer finish ----------------
__global__ void finish_kernel(const float* __restrict__ skip, int layer,
                              float* __restrict__ out, int to_out) {
  int i = blockIdx.x * blockDim.x + threadIdx.x;
  if (i >= NN * HH / 4) return;
  float sw = skip[layer];
  float alpha = 1.f / (1.f + __expf(-sw));
  float4 a0 = *(const float4*)&g_agg[i * 4];
  float4 x0 = *(const float4*)&g_x0[i * 4];
  float4 v;
  v.x = lkf(a0.x * (1.f / 3.f)) + alpha * x0.x;
  v.y = lkf(a0.y * (1.f / 3.f)) + alpha * x0.y;
  v.z = lkf(a0.z * (1.f / 3.f)) + alpha * x0.z;
  v.w = lkf(a0.w * (1.f / 3.f)) + alpha * x0.w;
  if (to_out) {
    *(float4*)&out[i * 4] = v;
  } else {
    __nv_bfloat162 lo = __floats2bfloat162_rn(v.x, v.y);
    __nv_bfloat162 hi = __floats2bfloat162_rn(v.z, v.w);
    uint2 u;
    u.x = *reinterpret_cast<uint32_t*>(&lo);
    u.y = *reinterpret_cast<uint32_t*>(&hi);
    *(uint2*)&g_xb[i * 4] = u;
  }
}

// ---------------- launch ----------------
extern "C" void kernel_launch(void* const* d_in, const int* in_sizes, int n_in,
                              void* d_out, int out_size) {
  const float* feat = (const float*)d_in[0];
  const float* emb = (const float*)d_in[1];
  const float* pw = (const float*)d_in[2];
  const float* pb = (const float*)d_in[3];
  const float* lng = (const float*)d_in[4];
  const float* lnb = (const float*)d_in[5];
  const float* skip = (const float*)d_in[6];
  const float* Wl = (const float*)d_in[7];
  const float* Wr = (const float*)d_in[8];
  const float* att = (const float*)d_in[9];
  const float* bias = (const float*)d_in[10];
  const int* esrc = (const int*)d_in[11];
  const int* edst = (const int*)d_in[12];
  float* out = (float*)d_out;

  cudaFuncSetAttribute(gemm_bf16_kernel, cudaFuncAttributeMaxDynamicSharedMemorySize,
                       GEMM_SMEM);
  void* aggp = nullptr;
  cudaGetSymbolAddress(&aggp, g_agg);

  convw_kernel<<<(NL * NT * 65536 + 255) / 256, 256>>>(Wl, Wr);
  precompute_kernel<<<NN / 16, 128>>>(feat, emb, pw, pb, lng, lnb);
  detect_kernel<<<1, 256>>>(edst);
  zero_cnt_kernel<<<(NT * NN + 255) / 256, 256>>>();
  hist_kernel<<<(NT * EE + 255) / 256, 256>>>(edst);
  scan_kernel<<<NT, 1024>>>();
  scatter_kernel<<<(NT * EE + 255) / 256, 256>>>(esrc, edst);

  for (int i = 0; i < NL; i++) {
    cudaMemsetAsync(aggp, 0, (size_t)NN * HH * sizeof(float));
    for (int t = 0; t < NT; t++) {
      gemm_bf16_kernel<<<dim3((NN + 127) / 128, 8), 256, GEMM_SMEM>>>(i, t);
      edge_attn_kernel<<<(NN * 32 + 255) / 256, 256>>>(i, t, att, bias);
    }
    finish_kernel<<<(NN * HH / 4 + 255) / 256, 256>>>(skip, i, out, i == 2 ? 1 : 0);
  }
}

// round 8
// speedup vs baseline: 1.0752x; 1.0752x over previous
#include <cuda_runtime.h>
#include <cuda_bf16.h>
#include <cstdint>

#define NN 50000
#define FIN 256
#define HH 128
#define NHEAD 4
#define NL 3
#define NT 3
#define EE 250000
#define NEG 0.2f

// ---------------- device scratch ----------------
__device__ __align__(16) float g_x0[NN * HH];
__device__ __align__(16) __nv_bfloat16 g_xb[NN * HH];
__device__ __align__(16) __nv_bfloat16 g_xlr[(size_t)NT * NN * 1024];  // [t][n][xl512|xr512]
__device__ __align__(16) __nv_bfloat16 g_wlb[NL * NT * 128 * 512];
__device__ __align__(16) __nv_bfloat16 g_wrb[NL * NT * 128 * 512];
__device__ __align__(16) float g_agg[NT * NN * HH];
__device__ int g_cnt[NT * NN];
__device__ int g_rs[NT * (NN + 1)];
__device__ int g_cur[NT * NN];
__device__ int g_csrc[NT * EE];
__device__ int g_is64;

__device__ __forceinline__ float lkf(float v) { return v > 0.f ? v : NEG * v; }

// ---------------- weight conversion f32 -> bf16 ----------------
__global__ void convw_kernel(const float* __restrict__ wl, const float* __restrict__ wr) {
  int i = blockIdx.x * 256 + threadIdx.x;
  if (i < NL * NT * 128 * 512) {
    g_wlb[i] = __float2bfloat16(wl[i]);
    g_wrb[i] = __float2bfloat16(wr[i]);
  }
}

// ---------------- precompute ----------------
__global__ void __launch_bounds__(128) precompute_kernel(
    const float* __restrict__ feat, const float* __restrict__ emb,
    const float* __restrict__ pw, const float* __restrict__ pb,
    const float* __restrict__ lng, const float* __restrict__ lnb) {
  __shared__ float sfeat[16][256];
  __shared__ float sh[16][132];
  const int tid = threadIdx.x;
  const int r0 = blockIdx.x * 16;

  for (int idx = tid; idx < 16 * 64; idx += 128) {
    int r = idx >> 6, k4 = idx & 63;
    float4 v = *(const float4*)&feat[(size_t)(r0 + r) * 256 + k4 * 4];
    *(float4*)&sfeat[r][k4 * 4] = v;
  }
  __syncthreads();

  float acc[16];
#pragma unroll
  for (int r = 0; r < 16; r++) acc[r] = 0.f;
  for (int k = 0; k < 256; k++) {
    float w = pw[k * 128 + tid];
#pragma unroll
    for (int r = 0; r < 16; r++) acc[r] = fmaf(sfeat[r][k], w, acc[r]);
  }
  float b = pb[tid];
#pragma unroll
  for (int r = 0; r < 16; r++) sh[r][tid] = acc[r] + b;
  __syncthreads();

  const int wid = tid >> 5, lane = tid & 31;
#pragma unroll 1
  for (int rr = 0; rr < 4; rr++) {
    int r = wid * 4 + rr;
    float v[4], e[4];
    float s = 0.f, s2 = 0.f, es = 0.f;
#pragma unroll
    for (int q = 0; q < 4; q++) {
      int c = lane + 32 * q;
      v[q] = sh[r][c];
      s += v[q];
      s2 += v[q] * v[q];
      e[q] = emb[(size_t)(r0 + r) * 128 + c];
      es += e[q] * e[q];
    }
#pragma unroll
    for (int off = 16; off; off >>= 1) {
      s += __shfl_xor_sync(0xffffffffu, s, off);
      s2 += __shfl_xor_sync(0xffffffffu, s2, off);
      es += __shfl_xor_sync(0xffffffffu, es, off);
    }
    float mu = s * (1.f / 128.f);
    float var = s2 * (1.f / 128.f) - mu * mu;
    float rst = rsqrtf(var + 1e-5f);
    float inv = 1.f / fmaxf(sqrtf(es), 1e-12f);
#pragma unroll
    for (int q = 0; q < 4; q++) {
      int c = lane + 32 * q;
      float hn = (v[q] - mu) * rst * lng[c] + lnb[c];
      float x0 = 0.7f * lkf(hn) + 0.5f * e[q] * inv;
      size_t o = (size_t)(r0 + r) * 128 + c;
      g_x0[o] = x0;
      g_xb[o] = __float2bfloat16(x0);
    }
  }
}

// ---------------- edge index dtype detection ----------------
__global__ void detect_kernel(const int* __restrict__ ed) {
  __shared__ int so;
  int tid = threadIdx.x;
  if (tid == 0) so = 0;
  __syncthreads();
  int o = 0;
  for (int i = tid; i < 4096; i += blockDim.x) o |= ed[2 * i + 1];
  atomicOr(&so, o);
  __syncthreads();
  if (tid == 0) g_is64 = (so == 0) ? 1 : 0;
}

__device__ __forceinline__ int load_idx(const int* p, int i, int is64) {
  return is64 ? (int)((const long long*)p)[i] : p[i];
}

// ---------------- CSR build ----------------
__global__ void zero_cnt_kernel() {
  int i = blockIdx.x * blockDim.x + threadIdx.x;
  if (i < NT * NN) g_cnt[i] = 0;
}

__global__ void hist_kernel(const int* __restrict__ edst) {
  int i = blockIdx.x * blockDim.x + threadIdx.x;
  if (i >= NT * EE) return;
  int is64 = g_is64;
  int t = i / EE;
  int d = load_idx(edst, i, is64);
  atomicAdd(&g_cnt[t * NN + d], 1);
}

__global__ void __launch_bounds__(1024) scan_kernel() {
  const int t = blockIdx.x;
  const int tid = threadIdx.x;
  __shared__ int sp[1024];
  const int C = (NN + 1023) / 1024;
  int b = tid * C;
  int e = min(b + C, NN);
  int s = 0;
  for (int v = b; v < e; v++) s += g_cnt[t * NN + v];
  sp[tid] = s;
  __syncthreads();
  for (int off = 1; off < 1024; off <<= 1) {
    int v = (tid >= off) ? sp[tid - off] : 0;
    __syncthreads();
    sp[tid] += v;
    __syncthreads();
  }
  int run = (tid ? sp[tid - 1] : 0);
  for (int v = b; v < e; v++) {
    g_rs[t * (NN + 1) + v] = run;
    g_cur[t * NN + v] = run;
    run += g_cnt[t * NN + v];
  }
  if (b < NN && e == NN) g_rs[t * (NN + 1) + NN] = run;
}

__global__ void scatter_kernel(const int* __restrict__ esrc, const int* __restrict__ edst) {
  int i = blockIdx.x * blockDim.x + threadIdx.x;
  if (i >= NT * EE) return;
  int is64 = g_is64;
  int t = i / EE;
  int d = load_idx(edst, i, is64);
  int slot = atomicAdd(&g_cur[t * NN + d], 1);
  g_csrc[t * EE + slot] = load_idx(esrc, i, is64);
}

// ---------------- bf16 tensor-core GEMM (m16n8k16 + ldmatrix) ----------------
#define AL 136
#define GEMM_SMEM (2 * 128 * AL * 2)

__global__ void __launch_bounds__(256, 2) gemm_bf16_kernel(int layer) {
  extern __shared__ __nv_bfloat16 sm[];
  __nv_bfloat16* sA = sm;             // [128][AL]
  __nv_bfloat16* sB = sm + 128 * AL;  // [128][AL]
  const int tid = threadIdx.x;
  const int lane = tid & 31;
  const int wid = tid >> 5;
  const int warpM = wid >> 2, warpN = wid & 3;
  const int g = lane >> 2, tg = lane & 3;
  const int m0 = blockIdx.x * 128;
  const int j0 = blockIdx.y * 128;
  const int t = j0 >> 10;
  const int lr = (j0 >> 9) & 1;
  const int col0 = j0 & 511;
  const __nv_bfloat16* Wg = (lr ? g_wrb : g_wlb) + (size_t)(layer * 3 + t) * 65536 + col0;

#pragma unroll
  for (int it = 0; it < 8; it++) {
    int idx = tid + it * 256;
    int m = idx >> 4, k8 = (idx & 15) * 8;
    uint4 v = make_uint4(0, 0, 0, 0);
    if (m0 + m < NN) v = *(const uint4*)&g_xb[(size_t)(m0 + m) * 128 + k8];
    *(uint4*)&sA[m * AL + k8] = v;
    uint4 w = *(const uint4*)&Wg[(size_t)m * 512 + k8];
    *(uint4*)&sB[m * AL + k8] = w;
  }
  __syncthreads();

  float acc[4][4][4];
#pragma unroll
  for (int im = 0; im < 4; im++)
#pragma unroll
    for (int in = 0; in < 4; in++)
#pragma unroll
      for (int q = 0; q < 4; q++) acc[im][in][q] = 0.f;

  uint32_t aBase = (uint32_t)__cvta_generic_to_shared(sA);
  uint32_t bBase = (uint32_t)__cvta_generic_to_shared(sB);
  const int lrow = lane & 15, lcol = (lane >> 4) * 8;

#pragma unroll
  for (int k0 = 0; k0 < 8; k0++) {
    uint32_t a[4][4];
#pragma unroll
    for (int im = 0; im < 4; im++) {
      uint32_t ad = aBase + ((warpM * 64 + im * 16 + lrow) * AL + k0 * 16 + lcol) * 2;
      asm volatile("ldmatrix.sync.aligned.m8n8.x4.shared.b16 {%0,%1,%2,%3},[%4];"
                   : "=r"(a[im][0]), "=r"(a[im][1]), "=r"(a[im][2]), "=r"(a[im][3])
                   : "r"(ad));
    }
    uint32_t b[4][2];
#pragma unroll
    for (int nb = 0; nb < 2; nb++) {
      uint32_t bd = bBase + ((k0 * 16 + lrow) * AL + warpN * 32 + nb * 16 + lcol) * 2;
      uint32_t r0, r1, r2, r3;
      asm volatile("ldmatrix.sync.aligned.m8n8.x4.trans.shared.b16 {%0,%1,%2,%3},[%4];"
                   : "=r"(r0), "=r"(r1), "=r"(r2), "=r"(r3)
                   : "r"(bd));
      b[nb * 2][0] = r0;
      b[nb * 2][1] = r1;
      b[nb * 2 + 1][0] = r2;
      b[nb * 2 + 1][1] = r3;
    }
#pragma unroll
    for (int im = 0; im < 4; im++)
#pragma unroll
      for (int in = 0; in < 4; in++) {
        asm volatile(
            "mma.sync.aligned.m16n8k16.row.col.f32.bf16.bf16.f32 "
            "{%0,%1,%2,%3},{%4,%5,%6,%7},{%8,%9},{%0,%1,%2,%3};"
            : "+f"(acc[im][in][0]), "+f"(acc[im][in][1]),
              "+f"(acc[im][in][2]), "+f"(acc[im][in][3])
            : "r"(a[im][0]), "r"(a[im][1]), "r"(a[im][2]), "r"(a[im][3]),
              "r"(b[in][0]), "r"(b[in][1]));
      }
  }
  __syncthreads();

#pragma unroll
  for (int im = 0; im < 4; im++)
#pragma unroll
    for (int in = 0; in < 4; in++) {
      int r = warpM * 64 + im * 16 + g;
      int c = warpN * 32 + in * 8 + tg * 2;
      *(__nv_bfloat162*)&sA[r * AL + c] =
          __floats2bfloat162_rn(acc[im][in][0], acc[im][in][1]);
      *(__nv_bfloat162*)&sA[(r + 8) * AL + c] =
          __floats2bfloat162_rn(acc[im][in][2], acc[im][in][3]);
    }
  __syncthreads();
#pragma unroll
  for (int it = 0; it < 8; it++) {
    int idx = tid + it * 256;
    int m = idx >> 4, n8 = (idx & 15) * 8;
    if (m0 + m < NN) {
      uint4 v = *(uint4*)&sA[m * AL + n8];
      *(uint4*)&g_xlr[((size_t)t * NN + (m0 + m)) * 1024 + lr * 512 + col0 + n8] = v;
    }
  }
}

// ---------------- edge attention: warp/node, head-major lanes, pairwise edges ----------
__device__ __forceinline__ void cvt16(const uint4& a, const uint4& b, float* o) {
  const uint32_t* u = &a.x;
#pragma unroll
  for (int q = 0; q < 4; q++) {
    float2 f = __bfloat1622float2(*reinterpret_cast<const __nv_bfloat162*>(&u[q]));
    o[q * 2] = f.x;
    o[q * 2 + 1] = f.y;
  }
  const uint32_t* v = &b.x;
#pragma unroll
  for (int q = 0; q < 4; q++) {
    float2 f = __bfloat1622float2(*reinterpret_cast<const __nv_bfloat162*>(&v[q]));
    o[8 + q * 2] = f.x;
    o[8 + q * 2 + 1] = f.y;
  }
}

__global__ void __launch_bounds__(256) edge_attn_kernel(int layer,
                                                        const float* __restrict__ att,
                                                        const float* __restrict__ bias_) {
  const int t = blockIdx.y;
  const int w = (blockIdx.x * blockDim.x + threadIdx.x) >> 5;
  const int lane = threadIdx.x & 31;
  if (w >= NN) return;
  const int h = lane >> 3;
  const int c0 = (lane & 7) * 16;
  const int hoff = h * 128 + c0;
  const __nv_bfloat16* base = g_xlr + (size_t)t * NN * 1024;

  float af[16], xr[16], acc[16];
  {
    const float* a = att + (size_t)(layer * 3 + t) * 512 + hoff;
#pragma unroll
    for (int q = 0; q < 4; q++) {
      float4 v = *(const float4*)&a[q * 4];
      af[q * 4] = v.x; af[q * 4 + 1] = v.y; af[q * 4 + 2] = v.z; af[q * 4 + 3] = v.w;
    }
    const uint4* xp = (const uint4*)(base + (size_t)w * 1024 + 512 + hoff);
    cvt16(xp[0], xp[1], xr);
#pragma unroll
    for (int i = 0; i < 16; i++) acc[i] = 0.f;
  }
  float mx = -3.0e38f, dn = 0.f;

  const int beg = g_rs[t * (NN + 1) + w];
  const int end = g_rs[t * (NN + 1) + w + 1];
  const int* csr = g_csrc + (size_t)t * EE;

  int j = beg;
  // pairwise main loop: 4 gathers in flight, one joint online-softmax update
  for (; j + 1 < end; j += 2) {
    int s0 = csr[j], s1 = csr[j + 1];
    const uint4* xp0 = (const uint4*)(base + (size_t)s0 * 1024 + hoff);
    const uint4* xp1 = (const uint4*)(base + (size_t)s1 * 1024 + hoff);
    uint4 a0 = xp0[0], a1 = xp0[1];
    uint4 b0 = xp1[0], b1 = xp1[1];
    float xl0[16], xl1[16];
    cvt16(a0, a1, xl0);
    cvt16(b0, b1, xl1);
    float p0 = 0.f, p1 = 0.f;
#pragma unroll
    for (int i = 0; i < 16; i++) {
      p0 = fmaf(af[i], lkf(xl0[i] + xr[i]), p0);
      p1 = fmaf(af[i], lkf(xl1[i] + xr[i]), p1);
    }
#pragma unroll
    for (int off = 1; off <= 4; off <<= 1) {
      p0 += __shfl_xor_sync(0xffffffffu, p0, off);
      p1 += __shfl_xor_sync(0xffffffffu, p1, off);
    }
    float nm = fmaxf(mx, fmaxf(p0, p1));
    float sc = __expf(mx - nm);
    float e0 = __expf(p0 - nm);
    float e1 = __expf(p1 - nm);
    mx = nm;
    dn = dn * sc + e0 + e1;
#pragma unroll
    for (int i = 0; i < 16; i++)
      acc[i] = fmaf(acc[i], sc, fmaf(e0, xl0[i], e1 * xl1[i]));
  }
  if (j < end) {  // tail edge
    int s0 = csr[j];
    const uint4* xp0 = (const uint4*)(base + (size_t)s0 * 1024 + hoff);
    uint4 a0 = xp0[0], a1 = xp0[1];
    float xl0[16];
    cvt16(a0, a1, xl0);
    float p0 = 0.f;
#pragma unroll
    for (int i = 0; i < 16; i++) p0 = fmaf(af[i], lkf(xl0[i] + xr[i]), p0);
#pragma unroll
    for (int off = 1; off <= 4; off <<= 1) p0 += __shfl_xor_sync(0xffffffffu, p0, off);
    float nm = fmaxf(mx, p0);
    float sc = __expf(mx - nm);
    float e0 = __expf(p0 - nm);
    mx = nm;
    dn = dn * sc + e0;
#pragma unroll
    for (int i = 0; i < 16; i++) acc[i] = fmaf(acc[i], sc, e0 * xl0[i]);
  }

  float s = (1.f / (dn + 1e-16f)) * 0.25f;
#pragma unroll
  for (int i = 0; i < 16; i++) acc[i] *= s;
  // head mean: butterfly over head bits (lanes ±8, ±16)
#pragma unroll
  for (int i = 0; i < 16; i++) {
    acc[i] += __shfl_xor_sync(0xffffffffu, acc[i], 8);
    acc[i] += __shfl_xor_sync(0xffffffffu, acc[i], 16);
  }
  if (h == 0) {
    const float* bs = bias_ + (size_t)(layer * 3 + t) * 128 + c0;
    float* dst = &g_agg[((size_t)t * NN + w) * 128 + c0];
#pragma unroll
    for (int q = 0; q < 4; q++) {
      float4 bv = *(const float4*)&bs[q * 4];
      float4 o = make_float4(acc[q * 4] + bv.x, acc[q * 4 + 1] + bv.y,
                             acc[q * 4 + 2] + bv.z, acc[q * 4 + 3] + bv.w);
      *(float4*)&dst[q * 4] = o;
    }
  }
}

// ---------------- layer finish ----------------
__global__ void finish_kernel(const float* __restrict__ skip, int layer,
                              float* __restrict__ out, int to_out) {
  int i = blockIdx.x * blockDim.x + threadIdx.x;
  if (i >= NN * HH / 4) return;
  float sw = skip[layer];
  float alpha = 1.f / (1.f + __expf(-sw));
  float4 a0 = *(const float4*)&g_agg[i * 4];
  float4 a1 = *(const float4*)&g_agg[NN * HH + i * 4];
  float4 a2 = *(const float4*)&g_agg[2 * NN * HH + i * 4];
  float4 x0 = *(const float4*)&g_x0[i * 4];
  float4 v;
  v.x = lkf((a0.x + a1.x + a2.x) * (1.f / 3.f)) + alpha * x0.x;
  v.y = lkf((a0.y + a1.y + a2.y) * (1.f / 3.f)) + alpha * x0.y;
  v.z = lkf((a0.z + a1.z + a2.z) * (1.f / 3.f)) + alpha * x0.z;
  v.w = lkf((a0.w + a1.w + a2.w) * (1.f / 3.f)) + alpha * x0.w;
  if (to_out) {
    *(float4*)&out[i * 4] = v;
  } else {
    __nv_bfloat162 lo = __floats2bfloat162_rn(v.x, v.y);
    __nv_bfloat162 hi = __floats2bfloat162_rn(v.z, v.w);
    uint2 u;
    u.x = *reinterpret_cast<uint32_t*>(&lo);
    u.y = *reinterpret_cast<uint32_t*>(&hi);
    *(uint2*)&g_xb[i * 4] = u;
  }
}

// ---------------- launch ----------------
extern "C" void kernel_launch(void* const* d_in, const int* in_sizes, int n_in,
                              void* d_out, int out_size) {
  const float* feat = (const float*)d_in[0];
  const float* emb = (const float*)d_in[1];
  const float* pw = (const float*)d_in[2];
  const float* pb = (const float*)d_in[3];
  const float* lng = (const float*)d_in[4];
  const float* lnb = (const float*)d_in[5];
  const float* skip = (const float*)d_in[6];
  const float* Wl = (const float*)d_in[7];
  const float* Wr = (const float*)d_in[8];
  const float* att = (const float*)d_in[9];
  const float* bias = (const float*)d_in[10];
  const int* esrc = (const int*)d_in[11];
  const int* edst = (const int*)d_in[12];
  float* out = (float*)d_out;

  cudaFuncSetAttribute(gemm_bf16_kernel, cudaFuncAttributeMaxDynamicSharedMemorySize,
                       GEMM_SMEM);

  convw_kernel<<<(NL * NT * 65536 + 255) / 256, 256>>>(Wl, Wr);
  precompute_kernel<<<NN / 16, 128>>>(feat, emb, pw, pb, lng, lnb);
  detect_kernel<<<1, 256>>>(edst);
  zero_cnt_kernel<<<(NT * NN + 255) / 256, 256>>>();
  hist_kernel<<<(NT * EE + 255) / 256, 256>>>(edst);
  scan_kernel<<<NT, 1024>>>();
  scatter_kernel<<<(NT * EE + 255) / 256, 256>>>(esrc, edst);

  for (int i = 0; i < NL; i++) {
    gemm_bf16_kernel<<<dim3((NN + 127) / 128, 3072 / 128), 256, GEMM_SMEM>>>(i);
    edge_attn_kernel<<<dim3((NN * 32 + 255) / 256, NT), 256>>>(i, att, bias);
    finish_kernel<<<(NN * HH / 4 + 255) / 256, 256>>>(skip, i, out, i == 2 ? 1 : 0);
  }
}

// round 10
// speedup vs baseline: 1.1970x; 1.1133x over previous
#include <cuda_runtime.h>
#include <cuda_bf16.h>
#include <cstdint>

#define NN 50000
#define FIN 256
#define HH 128
#define NHEAD 4
#define NL 3
#define NT 3
#define EE 250000
#define NEG 0.2f

// ---------------- device scratch ----------------
__device__ __align__(16) float g_x0[NN * HH];
__device__ __align__(16) __nv_bfloat16 g_xb[NN * HH];
__device__ __align__(16) __nv_bfloat16 g_xlr[(size_t)NT * NN * 1024];  // [t][n][xl512|xr512]
__device__ __align__(16) __nv_bfloat16 g_wlb[NL * NT * 128 * 512];
__device__ __align__(16) __nv_bfloat16 g_wrb[NL * NT * 128 * 512];
__device__ int g_cnt[NT * NN];
__device__ int g_rs[NT * (NN + 1)];
__device__ int g_cur[NT * NN];
__device__ int g_csrc[NT * EE];
__device__ int g_is64;

__device__ __forceinline__ float lkf(float v) { return v > 0.f ? v : NEG * v; }

// ---------------- weight conversion f32 -> bf16 ----------------
__global__ void convw_kernel(const float* __restrict__ wl, const float* __restrict__ wr) {
  int i = blockIdx.x * 256 + threadIdx.x;
  if (i < NL * NT * 128 * 512) {
    g_wlb[i] = __float2bfloat16(wl[i]);
    g_wrb[i] = __float2bfloat16(wr[i]);
  }
}

// ---------------- precompute ----------------
__global__ void __launch_bounds__(128) precompute_kernel(
    const float* __restrict__ feat, const float* __restrict__ emb,
    const float* __restrict__ pw, const float* __restrict__ pb,
    const float* __restrict__ lng, const float* __restrict__ lnb) {
  __shared__ float sfeat[16][256];
  __shared__ float sh[16][132];
  const int tid = threadIdx.x;
  const int r0 = blockIdx.x * 16;

  for (int idx = tid; idx < 16 * 64; idx += 128) {
    int r = idx >> 6, k4 = idx & 63;
    float4 v = *(const float4*)&feat[(size_t)(r0 + r) * 256 + k4 * 4];
    *(float4*)&sfeat[r][k4 * 4] = v;
  }
  __syncthreads();

  float acc[16];
#pragma unroll
  for (int r = 0; r < 16; r++) acc[r] = 0.f;
  for (int k = 0; k < 256; k++) {
    float w = pw[k * 128 + tid];
#pragma unroll
    for (int r = 0; r < 16; r++) acc[r] = fmaf(sfeat[r][k], w, acc[r]);
  }
  float b = pb[tid];
#pragma unroll
  for (int r = 0; r < 16; r++) sh[r][tid] = acc[r] + b;
  __syncthreads();

  const int wid = tid >> 5, lane = tid & 31;
#pragma unroll 1
  for (int rr = 0; rr < 4; rr++) {
    int r = wid * 4 + rr;
    float v[4], e[4];
    float s = 0.f, s2 = 0.f, es = 0.f;
#pragma unroll
    for (int q = 0; q < 4; q++) {
      int c = lane + 32 * q;
      v[q] = sh[r][c];
      s += v[q];
      s2 += v[q] * v[q];
      e[q] = emb[(size_t)(r0 + r) * 128 + c];
      es += e[q] * e[q];
    }
#pragma unroll
    for (int off = 16; off; off >>= 1) {
      s += __shfl_xor_sync(0xffffffffu, s, off);
      s2 += __shfl_xor_sync(0xffffffffu, s2, off);
      es += __shfl_xor_sync(0xffffffffu, es, off);
    }
    float mu = s * (1.f / 128.f);
    float var = s2 * (1.f / 128.f) - mu * mu;
    float rst = rsqrtf(var + 1e-5f);
    float inv = 1.f / fmaxf(sqrtf(es), 1e-12f);
#pragma unroll
    for (int q = 0; q < 4; q++) {
      int c = lane + 32 * q;
      float hn = (v[q] - mu) * rst * lng[c] + lnb[c];
      float x0 = 0.7f * lkf(hn) + 0.5f * e[q] * inv;
      size_t o = (size_t)(r0 + r) * 128 + c;
      g_x0[o] = x0;
      g_xb[o] = __float2bfloat16(x0);
    }
  }
}

// ---------------- edge index dtype detection ----------------
__global__ void detect_kernel(const int* __restrict__ ed) {
  __shared__ int so;
  int tid = threadIdx.x;
  if (tid == 0) so = 0;
  __syncthreads();
  int o = 0;
  for (int i = tid; i < 4096; i += blockDim.x) o |= ed[2 * i + 1];
  atomicOr(&so, o);
  __syncthreads();
  if (tid == 0) g_is64 = (so == 0) ? 1 : 0;
}

__device__ __forceinline__ int load_idx(const int* p, int i, int is64) {
  return is64 ? (int)((const long long*)p)[i] : p[i];
}

// ---------------- CSR build ----------------
__global__ void zero_cnt_kernel() {
  int i = blockIdx.x * blockDim.x + threadIdx.x;
  if (i < NT * NN) g_cnt[i] = 0;
}

__global__ void hist_kernel(const int* __restrict__ edst) {
  int i = blockIdx.x * blockDim.x + threadIdx.x;
  if (i >= NT * EE) return;
  int is64 = g_is64;
  int t = i / EE;
  int d = load_idx(edst, i, is64);
  atomicAdd(&g_cnt[t * NN + d], 1);
}

__global__ void __launch_bounds__(1024) scan_kernel() {
  const int t = blockIdx.x;
  const int tid = threadIdx.x;
  __shared__ int sp[1024];
  const int C = (NN + 1023) / 1024;
  int b = tid * C;
  int e = min(b + C, NN);
  int s = 0;
  for (int v = b; v < e; v++) s += g_cnt[t * NN + v];
  sp[tid] = s;
  __syncthreads();
  for (int off = 1; off < 1024; off <<= 1) {
    int v = (tid >= off) ? sp[tid - off] : 0;
    __syncthreads();
    sp[tid] += v;
    __syncthreads();
  }
  int run = (tid ? sp[tid - 1] : 0);
  for (int v = b; v < e; v++) {
    g_rs[t * (NN + 1) + v] = run;
    g_cur[t * NN + v] = run;
    run += g_cnt[t * NN + v];
  }
  if (b < NN && e == NN) g_rs[t * (NN + 1) + NN] = run;
}

__global__ void scatter_kernel(const int* __restrict__ esrc, const int* __restrict__ edst) {
  int i = blockIdx.x * blockDim.x + threadIdx.x;
  if (i >= NT * EE) return;
  int is64 = g_is64;
  int t = i / EE;
  int d = load_idx(edst, i, is64);
  int slot = atomicAdd(&g_cur[t * NN + d], 1);
  g_csrc[t * EE + slot] = load_idx(esrc, i, is64);
}

// ---------------- bf16 tensor-core GEMM (m16n8k16 + ldmatrix) ----------------
#define AL 136
#define GEMM_SMEM (2 * 128 * AL * 2)

__global__ void __launch_bounds__(256, 2) gemm_bf16_kernel(int layer) {
  extern __shared__ __nv_bfloat16 sm[];
  __nv_bfloat16* sA = sm;             // [128][AL]
  __nv_bfloat16* sB = sm + 128 * AL;  // [128][AL]
  const int tid = threadIdx.x;
  const int lane = tid & 31;
  const int wid = tid >> 5;
  const int warpM = wid >> 2, warpN = wid & 3;
  const int g = lane >> 2, tg = lane & 3;
  const int m0 = blockIdx.x * 128;
  const int j0 = blockIdx.y * 128;
  const int t = j0 >> 10;
  const int lr = (j0 >> 9) & 1;
  const int col0 = j0 & 511;
  const __nv_bfloat16* Wg = (lr ? g_wrb : g_wlb) + (size_t)(layer * 3 + t) * 65536 + col0;

#pragma unroll
  for (int it = 0; it < 8; it++) {
    int idx = tid + it * 256;
    int m = idx >> 4, k8 = (idx & 15) * 8;
    uint4 v = make_uint4(0, 0, 0, 0);
    if (m0 + m < NN) v = *(const uint4*)&g_xb[(size_t)(m0 + m) * 128 + k8];
    *(uint4*)&sA[m * AL + k8] = v;
    uint4 w = *(const uint4*)&Wg[(size_t)m * 512 + k8];
    *(uint4*)&sB[m * AL + k8] = w;
  }
  __syncthreads();

  float acc[4][4][4];
#pragma unroll
  for (int im = 0; im < 4; im++)
#pragma unroll
    for (int in = 0; in < 4; in++)
#pragma unroll
      for (int q = 0; q < 4; q++) acc[im][in][q] = 0.f;

  uint32_t aBase = (uint32_t)__cvta_generic_to_shared(sA);
  uint32_t bBase = (uint32_t)__cvta_generic_to_shared(sB);
  const int lrow = lane & 15, lcol = (lane >> 4) * 8;

#pragma unroll
  for (int k0 = 0; k0 < 8; k0++) {
    uint32_t a[4][4];
#pragma unroll
    for (int im = 0; im < 4; im++) {
      uint32_t ad = aBase + ((warpM * 64 + im * 16 + lrow) * AL + k0 * 16 + lcol) * 2;
      asm volatile("ldmatrix.sync.aligned.m8n8.x4.shared.b16 {%0,%1,%2,%3},[%4];"
                   : "=r"(a[im][0]), "=r"(a[im][1]), "=r"(a[im][2]), "=r"(a[im][3])
                   : "r"(ad));
    }
    uint32_t b[4][2];
#pragma unroll
    for (int nb = 0; nb < 2; nb++) {
      uint32_t bd = bBase + ((k0 * 16 + lrow) * AL + warpN * 32 + nb * 16 + lcol) * 2;
      uint32_t r0, r1, r2, r3;
      asm volatile("ldmatrix.sync.aligned.m8n8.x4.trans.shared.b16 {%0,%1,%2,%3},[%4];"
                   : "=r"(r0), "=r"(r1), "=r"(r2), "=r"(r3)
                   : "r"(bd));
      b[nb * 2][0] = r0;
      b[nb * 2][1] = r1;
      b[nb * 2 + 1][0] = r2;
      b[nb * 2 + 1][1] = r3;
    }
#pragma unroll
    for (int im = 0; im < 4; im++)
#pragma unroll
      for (int in = 0; in < 4; in++) {
        asm volatile(
            "mma.sync.aligned.m16n8k16.row.col.f32.bf16.bf16.f32 "
            "{%0,%1,%2,%3},{%4,%5,%6,%7},{%8,%9},{%0,%1,%2,%3};"
            : "+f"(acc[im][in][0]), "+f"(acc[im][in][1]),
              "+f"(acc[im][in][2]), "+f"(acc[im][in][3])
            : "r"(a[im][0]), "r"(a[im][1]), "r"(a[im][2]), "r"(a[im][3]),
              "r"(b[in][0]), "r"(b[in][1]));
      }
  }
  __syncthreads();

#pragma unroll
  for (int im = 0; im < 4; im++)
#pragma unroll
    for (int in = 0; in < 4; in++) {
      int r = warpM * 64 + im * 16 + g;
      int c = warpN * 32 + in * 8 + tg * 2;
      *(__nv_bfloat162*)&sA[r * AL + c] =
          __floats2bfloat162_rn(acc[im][in][0], acc[im][in][1]);
      *(__nv_bfloat162*)&sA[(r + 8) * AL + c] =
          __floats2bfloat162_rn(acc[im][in][2], acc[im][in][3]);
    }
  __syncthreads();
#pragma unroll
  for (int it = 0; it < 8; it++) {
    int idx = tid + it * 256;
    int m = idx >> 4, n8 = (idx & 15) * 8;
    if (m0 + m < NN) {
      uint4 v = *(uint4*)&sA[m * AL + n8];
      *(uint4*)&g_xlr[((size_t)t * NN + (m0 + m)) * 1024 + lr * 512 + col0 + n8] = v;
    }
  }
}

// ---------------- fused edge attention (3 types) + layer finish ----------------
__device__ __forceinline__ void cvt16(const uint4& a, const uint4& b, float* o) {
  const uint32_t* u = &a.x;
#pragma unroll
  for (int q = 0; q < 4; q++) {
    float2 f = __bfloat1622float2(*reinterpret_cast<const __nv_bfloat162*>(&u[q]));
    o[q * 2] = f.x;
    o[q * 2 + 1] = f.y;
  }
  const uint32_t* v = &b.x;
#pragma unroll
  for (int q = 0; q < 4; q++) {
    float2 f = __bfloat1622float2(*reinterpret_cast<const __nv_bfloat162*>(&v[q]));
    o[8 + q * 2] = f.x;
    o[8 + q * 2 + 1] = f.y;
  }
}

__global__ void __launch_bounds__(128) edgefin_kernel(int layer,
                                                      const float* __restrict__ att,
                                                      const float* __restrict__ bias_,
                                                      const float* __restrict__ skip,
                                                      float* __restrict__ out,
                                                      int to_out) {
  const int w = (blockIdx.x * 128 + threadIdx.x) >> 5;
  const int lane = threadIdx.x & 31;
  if (w >= NN) return;
  const int h = lane >> 3;
  const int c0 = (lane & 7) * 16;
  const int hoff = h * 128 + c0;

  float osum[16];
#pragma unroll
  for (int i = 0; i < 16; i++) osum[i] = 0.f;

#pragma unroll 1
  for (int t = 0; t < NT; t++) {
    const __nv_bfloat16* base = g_xlr + (size_t)t * NN * 1024;
    float af[16], xr[16], acc[16];
    {
      const float* a = att + (size_t)(layer * 3 + t) * 512 + hoff;
#pragma unroll
      for (int q = 0; q < 4; q++) {
        float4 v = *(const float4*)&a[q * 4];
        af[q * 4] = v.x; af[q * 4 + 1] = v.y; af[q * 4 + 2] = v.z; af[q * 4 + 3] = v.w;
      }
      const uint4* xp = (const uint4*)(base + (size_t)w * 1024 + 512 + hoff);
      cvt16(xp[0], xp[1], xr);
#pragma unroll
      for (int i = 0; i < 16; i++) acc[i] = 0.f;
    }
    float mx = -3.0e38f, dn = 0.f;
    const int beg = g_rs[t * (NN + 1) + w];
    const int end = g_rs[t * (NN + 1) + w + 1];
    const int* csr = g_csrc + (size_t)t * EE;

    int j = beg;
    for (; j + 1 < end; j += 2) {
      int s0 = csr[j], s1 = csr[j + 1];
      const uint4* xp0 = (const uint4*)(base + (size_t)s0 * 1024 + hoff);
      const uint4* xp1 = (const uint4*)(base + (size_t)s1 * 1024 + hoff);
      uint4 a0 = xp0[0], a1 = xp0[1];
      uint4 b0 = xp1[0], b1 = xp1[1];
      float xl0[16], xl1[16];
      cvt16(a0, a1, xl0);
      cvt16(b0, b1, xl1);
      float p0 = 0.f, p1 = 0.f;
#pragma unroll
      for (int i = 0; i < 16; i++) {
        p0 = fmaf(af[i], lkf(xl0[i] + xr[i]), p0);
        p1 = fmaf(af[i], lkf(xl1[i] + xr[i]), p1);
      }
#pragma unroll
      for (int off = 1; off <= 4; off <<= 1) {
        p0 += __shfl_xor_sync(0xffffffffu, p0, off);
        p1 += __shfl_xor_sync(0xffffffffu, p1, off);
      }
      float nm = fmaxf(mx, fmaxf(p0, p1));
      float sc = __expf(mx - nm);
      float e0 = __expf(p0 - nm);
      float e1 = __expf(p1 - nm);
      mx = nm;
      dn = dn * sc + e0 + e1;
#pragma unroll
      for (int i = 0; i < 16; i++)
        acc[i] = fmaf(acc[i], sc, fmaf(e0, xl0[i], e1 * xl1[i]));
    }
    if (j < end) {
      int s0 = csr[j];
      const uint4* xp0 = (const uint4*)(base + (size_t)s0 * 1024 + hoff);
      uint4 a0 = xp0[0], a1 = xp0[1];
      float xl0[16];
      cvt16(a0, a1, xl0);
      float p0 = 0.f;
#pragma unroll
      for (int i = 0; i < 16; i++) p0 = fmaf(af[i], lkf(xl0[i] + xr[i]), p0);
#pragma unroll
      for (int off = 1; off <= 4; off <<= 1) p0 += __shfl_xor_sync(0xffffffffu, p0, off);
      float nm = fmaxf(mx, p0);
      float sc = __expf(mx - nm);
      float e0 = __expf(p0 - nm);
      mx = nm;
      dn = dn * sc + e0;
#pragma unroll
      for (int i = 0; i < 16; i++) acc[i] = fmaf(acc[i], sc, e0 * xl0[i]);
    }

    float s = (1.f / (dn + 1e-16f)) * 0.25f;
#pragma unroll
    for (int i = 0; i < 16; i++) osum[i] = fmaf(acc[i], s, osum[i]);
  }

  // head mean across the 4 head-lane groups (lanes ±8, ±16)
#pragma unroll
  for (int i = 0; i < 16; i++) {
    osum[i] += __shfl_xor_sync(0xffffffffu, osum[i], 8);
    osum[i] += __shfl_xor_sync(0xffffffffu, osum[i], 16);
  }

  if (h == 0) {
    float alpha = 1.f / (1.f + __expf(-skip[layer]));
    float bsum[16];
#pragma unroll
    for (int i = 0; i < 16; i++) bsum[i] = 0.f;
#pragma unroll
    for (int t = 0; t < NT; t++) {
      const float* bs = bias_ + (size_t)(layer * 3 + t) * 128 + c0;
#pragma unroll
      for (int q = 0; q < 4; q++) {
        float4 bv = *(const float4*)&bs[q * 4];
        bsum[q * 4] += bv.x; bsum[q * 4 + 1] += bv.y;
        bsum[q * 4 + 2] += bv.z; bsum[q * 4 + 3] += bv.w;
      }
    }
    const float* x0p = &g_x0[(size_t)w * 128 + c0];
    if (to_out) {
      float* dst = &out[(size_t)w * 128 + c0];
#pragma unroll
      for (int q = 0; q < 4; q++) {
        float4 x0 = *(const float4*)&x0p[q * 4];
        float4 v;
        v.x = lkf((osum[q * 4 + 0] + bsum[q * 4 + 0]) * (1.f / 3.f)) + alpha * x0.x;
        v.y = lkf((osum[q * 4 + 1] + bsum[q * 4 + 1]) * (1.f / 3.f)) + alpha * x0.y;
        v.z = lkf((osum[q * 4 + 2] + bsum[q * 4 + 2]) * (1.f / 3.f)) + alpha * x0.z;
        v.w = lkf((osum[q * 4 + 3] + bsum[q * 4 + 3]) * (1.f / 3.f)) + alpha * x0.w;
        *(float4*)&dst[q * 4] = v;
      }
    } else {
      __nv_bfloat16* dst = &g_xb[(size_t)w * 128 + c0];
#pragma unroll
      for (int q = 0; q < 4; q++) {
        float4 x0 = *(const float4*)&x0p[q * 4];
        float4 v;
        v.x = lkf((osum[q * 4 + 0] + bsum[q * 4 + 0]) * (1.f / 3.f)) + alpha * x0.x;
        v.y = lkf((osum[q * 4 + 1] + bsum[q * 4 + 1]) * (1.f / 3.f)) + alpha * x0.y;
        v.z = lkf((osum[q * 4 + 2] + bsum[q * 4 + 2]) * (1.f / 3.f)) + alpha * x0.z;
        v.w = lkf((osum[q * 4 + 3] + bsum[q * 4 + 3]) * (1.f / 3.f)) + alpha * x0.w;
        __nv_bfloat162 lo = __floats2bfloat162_rn(v.x, v.y);
        __nv_bfloat162 hi = __floats2bfloat162_rn(v.z, v.w);
        uint2 u;
        u.x = *reinterpret_cast<uint32_t*>(&lo);
        u.y = *reinterpret_cast<uint32_t*>(&hi);
        *(uint2*)&dst[q * 4] = u;
      }
    }
  }
}

// ---------------- launch ----------------
extern "C" void kernel_launch(void* const* d_in, const int* in_sizes, int n_in,
                              void* d_out, int out_size) {
  const float* feat = (const float*)d_in[0];
  const float* emb = (const float*)d_in[1];
  const float* pw = (const float*)d_in[2];
  const float* pb = (const float*)d_in[3];
  const float* lng = (const float*)d_in[4];
  const float* lnb = (const float*)d_in[5];
  const float* skip = (const float*)d_in[6];
  const float* Wl = (const float*)d_in[7];
  const float* Wr = (const float*)d_in[8];
  const float* att = (const float*)d_in[9];
  const float* bias = (const float*)d_in[10];
  const int* esrc = (const int*)d_in[11];
  const int* edst = (const int*)d_in[12];
  float* out = (float*)d_out;

  cudaFuncSetAttribute(gemm_bf16_kernel, cudaFuncAttributeMaxDynamicSharedMemorySize,
                       GEMM_SMEM);

  convw_kernel<<<(NL * NT * 65536 + 255) / 256, 256>>>(Wl, Wr);
  precompute_kernel<<<NN / 16, 128>>>(feat, emb, pw, pb, lng, lnb);
  detect_kernel<<<1, 256>>>(edst);
  zero_cnt_kernel<<<(NT * NN + 255) / 256, 256>>>();
  hist_kernel<<<(NT * EE + 255) / 256, 256>>>(edst);
  scan_kernel<<<NT, 1024>>>();
  scatter_kernel<<<(NT * EE + 255) / 256, 256>>>(esrc, edst);

  for (int i = 0; i < NL; i++) {
    gemm_bf16_kernel<<<dim3((NN + 127) / 128, 3072 / 128), 256, GEMM_SMEM>>>(i);
    edgefin_kernel<<<(NN * 32 + 127) / 128, 128>>>(i, att, bias, skip, out,
                                                   i == 2 ? 1 : 0);
  }
}